// round 13
// baseline (speedup 1.0000x reference)
#include <cuda_runtime.h>
#include <cuda_fp16.h>
#include <math.h>
#include <stdint.h>

#define BB_ 32
#define T_ 128
#define D_ 128
#define H_ 132
#define O_ 64

#define NSTRIDE 24                    // fp16 per n-row (48B): [16 k-vals][8B pad] -> ldmatrix conflict-free
#define WCH_AB (144 * 48)             // 6912 B per k-step chunk (N=144)
#define WCH_C  (64 * 48)              // 3072 B per k-step chunk (N=64)
#define WBYTES_A (8 * WCH_AB)         // 55296
#define WBYTES_B (9 * WCH_AB)         // 62208
#define WBYTES_C (9 * WCH_C)          // 27648

// ---------------- main-kernel SMEM layout (persistent, all weights resident) ----------------
#define OFF_X   0                     // 9 ksteps x 256 rows x 32B = 73728
#define OFF_WA  73728                 // -> 129024
#define OFF_WB  129024                // -> 191232
#define OFF_WC  191232                // -> 218880
#define OFF_B2  218880                // 144 floats -> 219456
#define OFF_B3  219456                // 64 floats  -> 219712
#define OFF_RED OFF_X                 // sRed (8192B) ALIASES X tile; used only after stage C
#define SMEM_TOTAL 219712

// ---------------- PW-kernel SMEM layout ----------------
#define PWK_W   36864                 // W at 36864 (55296) -> 92160
#define PWK_XL  92160                 // Xl (32768) -> 124928
#define PWK_B1  124928                // 144 floats -> 125504
#define PWK_SMEM 125504

#define NTILE 1088                    // sum_t ceil((128-t)/8)

// ---------------- device scratch ----------------
__device__ float g_pre8[T_ * 16 * BB_ * D_];   // [t][c][bb][d] prefix max over [t, t+8(c+1))
__device__ float g_PW[T_ * BB_ * 144];         // [s][bb][n]: P(s,bb)·W1[128:256] + b1
__device__ __half g_W1h[8 * 144 * NSTRIDE];    // [kstep][n][24], W1 rows 0..127 (M part), fp16
__device__ __half g_W1pw[8 * 144 * NSTRIDE];   // [kstep][n][24], W1 rows 128..255 (P part), fp16
__device__ __half g_W2h[9 * 144 * NSTRIDE];
__device__ __half g_W3h[9 * 64 * NSTRIDE];
__device__ int g_map[NTILE];                   // packed (t<<8)|c

// ---------------- asm helpers ----------------
__device__ __forceinline__ void mma_f16(float d[4], const uint32_t a[4], const uint32_t b[2]) {
    asm volatile("mma.sync.aligned.m16n8k16.row.col.f32.f16.f16.f32 "
                 "{%0,%1,%2,%3}, {%4,%5,%6,%7}, {%8,%9}, {%0,%1,%2,%3};"
                 : "+f"(d[0]), "+f"(d[1]), "+f"(d[2]), "+f"(d[3])
                 : "r"(a[0]), "r"(a[1]), "r"(a[2]), "r"(a[3]), "r"(b[0]), "r"(b[1]));
}
__device__ __forceinline__ uint32_t smem_u32(const void* p) {
    uint32_t a;
    asm("{ .reg .u64 t; cvta.to.shared.u64 t, %1; cvt.u32.u64 %0, t; }" : "=r"(a) : "l"(p));
    return a;
}
#define CP16(dst, src) asm volatile("cp.async.ca.shared.global [%0], [%1], 16;" :: "r"(dst), "l"(src) : "memory")
#define CP_COMMIT()    asm volatile("cp.async.commit_group;" ::: "memory")
#define CP_WAIT0()     asm volatile("cp.async.wait_group 0;" ::: "memory")
#define LDSM4(r, a) asm volatile("ldmatrix.sync.aligned.m8n8.x4.shared.b16 {%0,%1,%2,%3}, [%4];" \
    : "=r"((r)[0]), "=r"((r)[1]), "=r"((r)[2]), "=r"((r)[3]) : "r"(a))
#define LDSM2(r, a) asm volatile("ldmatrix.sync.aligned.m8n8.x2.shared.b16 {%0,%1}, [%2];" \
    : "=r"((r)[0]), "=r"((r)[1]) : "r"(a))

// ---------------- prep: fp16 weights, N padded to 144, 48B n-stride ----------------
__global__ void prep_weights(const float* __restrict__ W1, const float* __restrict__ W2,
                             const float* __restrict__ W3) {
    int i = blockIdx.x * blockDim.x + threadIdx.x;
    if (i < 8 * 144 * NSTRIDE) {
        int ks = i / (144 * NSTRIDE), r = i % (144 * NSTRIDE);
        int n = r / NSTRIDE, kk = r % NSTRIDE;
        __half o = __float2half(0.f), o2 = o;
        if (kk < 16 && n < H_) {
            o  = __float2half(W1[(ks * 16 + kk) * H_ + n]);
            o2 = __float2half(W1[(128 + ks * 16 + kk) * H_ + n]);
        }
        g_W1h[i] = o;
        g_W1pw[i] = o2;
    }
    if (i < 9 * 144 * NSTRIDE) {
        int ks = i / (144 * NSTRIDE), r = i % (144 * NSTRIDE);
        int n = r / NSTRIDE, kk = r % NSTRIDE;
        int k = ks * 16 + kk;
        __half o = __float2half(0.f);
        if (kk < 16 && n < H_ && k < H_) o = __float2half(W2[k * H_ + n]);
        g_W2h[i] = o;
    }
    if (i < 9 * 64 * NSTRIDE) {
        int ks = i / (64 * NSTRIDE), r = i % (64 * NSTRIDE);
        int n = r / NSTRIDE, kk = r % NSTRIDE;
        int k = ks * 16 + kk;
        __half o = __float2half(0.f);
        if (kk < 16 && k < H_) o = __float2half(W3[k * O_ + n]);
        g_W3h[i] = o;
    }
}

// ---------------- tile map: linear index -> (t, c), 8-s chunks ----------------
__global__ void build_map() {
    int t = threadIdx.x;               // 128 threads
    int start = 0;
    for (int u = 0; u < t; ++u) start += (135 - u) >> 3;
    int nch = (135 - t) >> 3;
    for (int c2 = 0; c2 < nch; ++c2) g_map[start + c2] = (t << 8) | c2;
}

// ---------------- prefix max at 8-step boundaries (+ out init folded in) ----------------
__global__ void compute_pre_kernel(const float* __restrict__ P, float* __restrict__ out) {
    int idx = blockIdx.x * blockDim.x + threadIdx.x;
    if (idx < BB_ * T_ * O_) out[idx] = 0.f;
    int t = idx >> 12, bb = (idx >> 7) & 31, d = idx & 127;
    const float* Pp = P + bb * (T_ * D_) + d;
    float run = -3.4e38f;
    for (int s = t; s < T_; ++s) {
        run = fmaxf(run, Pp[s * D_]);
        int m = s - t + 1;
        if ((m & 7) == 0) {
            int ci = (m >> 3) - 1;
            if (ci < 16) g_pre8[((t * 16 + ci) * BB_ + bb) * D_ + d] = run;
        }
    }
}

// ---------------- barrier-free GEMM stage; XSTR = X bytes per k-step ----------------
template <int K16, int NT, int CHUNK, int XSTR>
__device__ __forceinline__ void gemm_stage(uint32_t wbase, float (*acc)[4],
                                           const uint32_t aH[2], const uint32_t* bOff) {
    #pragma unroll
    for (int k = 0; k < K16; ++k) {
        uint32_t wb = wbase + k * CHUNK;
        uint32_t ah[2][4];
        LDSM4(ah[0], aH[0] + k * XSTR);
        LDSM4(ah[1], aH[1] + k * XSTR);
        uint32_t b[2 * NT];
        if (NT == 9) {
            LDSM4(b, wb + bOff[0]); LDSM4(b + 4, wb + bOff[1]);
            LDSM4(b + 8, wb + bOff[2]); LDSM4(b + 12, wb + bOff[3]);
            LDSM2(b + 16, wb + bOff[4]);
        } else {
            LDSM4(b, wb + bOff[0]); LDSM4(b + 4, wb + bOff[1]);
        }
        #pragma unroll
        for (int j = 0; j < NT; ++j) { mma_f16(acc[j], ah[0], b + 2 * j); mma_f16(acc[NT + j], ah[1], b + 2 * j); }
    }
}

// ---------------- bulk weight loader ----------------
__device__ __forceinline__ void load_chunk(uint32_t dst, const char* Wg, int bytes, int tid, int nth) {
    for (int off = tid * 16; off < bytes; off += nth * 16)
        CP16(dst + off, Wg + off);
    CP_COMMIT();
}

// ---------------- PW via tensor cores: g_PW[s][bb][n] = P·W1[128:256] + b1 ----------------
__global__ void __launch_bounds__(256, 1)
compute_pw_mma(const float* __restrict__ P, const float* __restrict__ b1) {
    const int s4 = blockIdx.x;          // s = s4*4 + sl
    extern __shared__ char smem[];
    uint32_t su = smem_u32(smem);
    const int tid = threadIdx.x;
    float* sB1 = (float*)(smem + PWK_B1);

    load_chunk(su + PWK_W, (const char*)g_W1pw, WBYTES_A, tid, 256);
    for (int i = tid; i < 144; i += 256) sB1[i] = (i < H_) ? b1[i] : 0.f;

    // X build: hi/lo fp16 of P, vectorized (128 rows, 4096 B per kstep)
    {
        int p = tid & 63, g = tid >> 6;
        int d0 = 2 * p, ks = d0 >> 4, kk = d0 & 15;
        char* xh = smem;
        char* xl = smem + PWK_XL;
        for (int b8 = 0; b8 < 8; ++b8) {
            int bb = g * 8 + b8;
            #pragma unroll
            for (int sl = 0; sl < 4; ++sl) {
                int s = s4 * 4 + sl;
                float2 pv = *(const float2*)&P[(bb * T_ + s) * D_ + d0];
                int row = sl * 32 + bb;
                int ph = (kk >> 3) ^ ((row >> 2) & 1);
                int off = ks * 4096 + row * 32 + ph * 16 + (kk & 7) * 2;
                __half2 h, l;
                h.x = __float2half(pv.x); h.y = __float2half(pv.y);
                l.x = __float2half(pv.x - __half2float(h.x));
                l.y = __float2half(pv.y - __half2float(h.y));
                *(__half2*)(xh + off) = h;
                *(__half2*)(xl + off) = l;
            }
        }
    }
    CP_WAIT0();
    __syncthreads();

    const int wid = tid >> 5, lane = tid & 31;
    const int mq = wid >> 1, nq = wid & 1;
    const int m0 = mq * 16;
    const int grp = lane >> 2, c0 = 2 * (lane & 3);

    uint32_t aH[2], aL[2], bAB[5];
    {
        int l15 = lane & 15, chnk = lane >> 4;
        #pragma unroll
        for (int mt = 0; mt < 2; ++mt) {
            int row = m0 + mt * 64 + l15;
            int phys = chnk ^ ((row >> 2) & 1);
            aH[mt] = su + row * 32 + phys * 16;
            aL[mt] = aH[mt] + PWK_XL;
        }
        int l7 = lane & 7, kh = (lane >> 3) & 1, pr = (lane >> 4) & 1;
        #pragma unroll
        for (int i = 0; i < 4; ++i)
            bAB[i] = (uint32_t)((nq * 72 + 16 * i + pr * 8 + l7) * 48 + kh * 16);
        bAB[4] = (uint32_t)((nq * 72 + 64 + l7) * 48 + kh * 16);
    }

    float acc[18][4];
    #pragma unroll
    for (int i = 0; i < 18; ++i) { acc[i][0] = acc[i][1] = acc[i][2] = acc[i][3] = 0.f; }
    gemm_stage<8, 9, WCH_AB, 4096>(su + PWK_W, acc, aH, bAB);   // hi pass
    gemm_stage<8, 9, WCH_AB, 4096>(su + PWK_W, acc, aL, bAB);   // lo pass

    #pragma unroll
    for (int mt = 0; mt < 2; ++mt)
    #pragma unroll
    for (int rp = 0; rp < 2; ++rp) {
        int row = m0 + mt * 64 + grp + rp * 8;
        int sl = row >> 5, bb = row & 31;
        int s = s4 * 4 + sl;
        #pragma unroll
        for (int j = 0; j < 9; ++j) {
            int n0 = nq * 72 + j * 8 + c0;
            float2 v;
            v.x = acc[mt * 9 + j][rp * 2 + 0] + sB1[n0];
            v.y = acc[mt * 9 + j][rp * 2 + 1] + sB1[n0 + 1];
            *(float2*)&g_PW[(s * BB_ + bb) * 144 + n0] = v;
        }
    }
}

// ---------------- relu epilogue (256-row tile): write fp16 X tile for next stage ----------------
__device__ __forceinline__ void epi_relu(char* smem, float (*acc)[4], const float* bias,
                                         int m0, int nbase, int lane) {
    char* xh = smem + OFF_X;
    const int grp = lane >> 2;
    const int c0 = 2 * (lane & 3);
    #pragma unroll
    for (int mt = 0; mt < 2; ++mt)
    #pragma unroll
    for (int j = 0; j < 9; ++j) {
        int n0 = nbase + j * 8 + c0;
        float bv0 = bias ? bias[n0] : 0.f;
        float bv1 = bias ? bias[n0 + 1] : 0.f;
        int ks = n0 >> 4, kk = n0 & 15;
        #pragma unroll
        for (int rp = 0; rp < 2; ++rp) {
            int row = m0 + mt * 128 + grp + rp * 8;
            float v0 = fmaxf(acc[mt * 9 + j][rp * 2 + 0] + bv0, 0.f);
            float v1 = fmaxf(acc[mt * 9 + j][rp * 2 + 1] + bv1, 0.f);
            __half2 hp; hp.x = __float2half(v0); hp.y = __float2half(v1);
            int ph = (kk >> 3) ^ ((row >> 2) & 1);
            *(__half2*)(xh + ks * 8192 + row * 32 + ph * 16 + (kk & 7) * 2) = hp;
        }
    }
}

// ---------------- main: persistent, all weights resident, M=256 tiles ----------------
__global__ void __launch_bounds__(512, 1)
mlp_main_kernel(const float* __restrict__ P,
                const float* __restrict__ b2, const float* __restrict__ b3,
                float* __restrict__ out) {
    extern __shared__ char smem[];
    uint32_t su = smem_u32(smem);
    const int tid = threadIdx.x;
    float* sB2 = (float*)(smem + OFF_B2);
    float* sB3 = (float*)(smem + OFF_B3);
    int* sRed = (int*)(smem + OFF_RED);    // ALIASES X tile; valid only after stage C

    // load ALL stage weights once (3 commit groups)
    load_chunk(su + OFF_WA, (const char*)g_W1h, WBYTES_A, tid, 512);
    load_chunk(su + OFF_WB, (const char*)g_W2h, WBYTES_B, tid, 512);
    load_chunk(su + OFF_WC, (const char*)g_W3h, WBYTES_C, tid, 512);
    for (int i = tid; i < 144; i += 512) sB2[i] = (i < H_) ? b2[i] : 0.f;
    if (tid < 64) sB3[tid] = b3[tid];

    const int wid = tid >> 5, lane = tid & 31;
    const int mq = wid >> 1, nq = wid & 1;      // 8 m-quads x 2 n-halves; m-tiles at m0, m0+128
    const int m0 = mq * 16;
    const int grp = lane >> 2, c0 = 2 * (lane & 3);

    // per-lane ldmatrix addresses (tile-invariant)
    uint32_t aH[2], bAB[5], bC[2];
    {
        int l15 = lane & 15, chnk = lane >> 4;
        #pragma unroll
        for (int mt = 0; mt < 2; ++mt) {
            int row = m0 + mt * 128 + l15;
            int phys = chnk ^ ((row >> 2) & 1);
            aH[mt] = su + OFF_X + row * 32 + phys * 16;
        }
        int l7 = lane & 7, kh = (lane >> 3) & 1, pr = (lane >> 4) & 1;
        #pragma unroll
        for (int i = 0; i < 4; ++i)
            bAB[i] = (uint32_t)((nq * 72 + 16 * i + pr * 8 + l7) * 48 + kh * 16);
        bAB[4] = (uint32_t)((nq * 72 + 64 + l7) * 48 + kh * 16);
        #pragma unroll
        for (int i = 0; i < 2; ++i)
            bC[i] = (uint32_t)((nq * 32 + 16 * i + pr * 8 + l7) * 48 + kh * 16);
    }

    // feature-build thread map (tile-invariant)
    const int fp = tid & 63, fg = tid >> 6;
    const int fd0 = 2 * fp, fks = fd0 >> 4, fkk = fd0 & 15;

    bool first = true;
    for (int it = blockIdx.x; it < NTILE; it += gridDim.x) {
        const int mc = g_map[it];
        const int t = mc >> 8;
        const int c = mc & 255;
        const int s0 = t + 8 * c;

        // feature build: rows r = sl*32+bb (sl 0..7); K cols [0,128) = running max, fp16
        {
            char* xh = smem + OFF_X;
            #pragma unroll
            for (int b4 = 0; b4 < 4; ++b4) {
                int bb = fg * 4 + b4;
                float2 run2;
                if (c > 0) run2 = *(const float2*)&g_pre8[((t * 16 + (c - 1)) * BB_ + bb) * D_ + fd0];
                else { run2.x = -3.4e38f; run2.y = -3.4e38f; }
                #pragma unroll
                for (int sl = 0; sl < 8; ++sl) {
                    int s = s0 + sl;
                    if (s < T_) {
                        float2 pv = *(const float2*)&P[(bb * T_ + s) * D_ + fd0];
                        run2.x = fmaxf(run2.x, pv.x);
                        run2.y = fmaxf(run2.y, pv.y);
                    }
                    int row = sl * 32 + bb;
                    int ph = (fkk >> 3) ^ ((row >> 2) & 1);
                    __half2 hp; hp.x = __float2half(run2.x); hp.y = __float2half(run2.y);
                    *(__half2*)(xh + fks * 8192 + row * 32 + ph * 16 + (fkk & 7) * 2) = hp;
                }
            }
        }

        float acc[18][4];
        // Stage A acc preload from PW (P-part + b1, fp32)
        #pragma unroll
        for (int mt = 0; mt < 2; ++mt) {
            int r_lo = m0 + mt * 128 + grp, r_hi = r_lo + 8;
            int s_lo = min(s0 + (r_lo >> 5), T_ - 1), s_hi = min(s0 + (r_hi >> 5), T_ - 1);
            const float* pwlo = g_PW + (s_lo * BB_ + (r_lo & 31)) * 144;
            const float* pwhi = g_PW + (s_hi * BB_ + (r_hi & 31)) * 144;
            #pragma unroll
            for (int j = 0; j < 9; ++j) {
                int n0 = nq * 72 + j * 8 + c0;
                float2 vlo = *(const float2*)(pwlo + n0);
                float2 vhi = *(const float2*)(pwhi + n0);
                acc[mt * 9 + j][0] = vlo.x; acc[mt * 9 + j][1] = vlo.y;
                acc[mt * 9 + j][2] = vhi.x; acc[mt * 9 + j][3] = vhi.y;
            }
        }
        if (first) { CP_WAIT0(); first = false; }
        __syncthreads();

        // Stage A: K=128 (8 ksteps), N=144
        gemm_stage<8, 9, WCH_AB, 8192>(su + OFF_WA, acc, aH, bAB);
        __syncthreads();
        epi_relu(smem, acc, (const float*)0, m0, nq * 72, lane);
        __syncthreads();

        // Stage B: K=144 (9 ksteps), N=144
        #pragma unroll
        for (int i = 0; i < 18; ++i) { acc[i][0] = acc[i][1] = acc[i][2] = acc[i][3] = 0.f; }
        gemm_stage<9, 9, WCH_AB, 8192>(su + OFF_WB, acc, aH, bAB);
        __syncthreads();
        epi_relu(smem, acc, sB2, m0, nq * 72, lane);
        __syncthreads();

        // Stage C: K=144 (9 ksteps), N=64
        #pragma unroll
        for (int i = 0; i < 8; ++i) { acc[i][0] = acc[i][1] = acc[i][2] = acc[i][3] = 0.f; }
        gemm_stage<9, 4, WCH_C, 8192>(su + OFF_WC, acc, aH, bC);
        __syncthreads();                 // X dead; safe to alias sRed

        for (int i = tid; i < BB_ * O_; i += 512) sRed[i] = 0;
        __syncthreads();

        // final epilogue: sigmoid + max reduce
        #pragma unroll
        for (int mt = 0; mt < 2; ++mt)
        #pragma unroll
        for (int rp = 0; rp < 2; ++rp) {
            int row = m0 + mt * 128 + grp + rp * 8;
            int sl = row >> 5, bb = row & 31;
            if (s0 + sl < T_) {
                #pragma unroll
                for (int j = 0; j < 4; ++j) {
                    int n0 = nq * 32 + j * 8 + c0;
                    float y0 = 1.f / (1.f + __expf(-5.f * (acc[mt * 4 + j][rp * 2 + 0] + sB3[n0])));
                    float y1 = 1.f / (1.f + __expf(-5.f * (acc[mt * 4 + j][rp * 2 + 1] + sB3[n0 + 1])));
                    atomicMax(&sRed[bb * O_ + n0], __float_as_int(y0));
                    atomicMax(&sRed[bb * O_ + n0 + 1], __float_as_int(y1));
                }
            }
        }
        __syncthreads();
        for (int i = tid; i < BB_ * O_; i += 512) {
            int bb = i >> 6, o = i & 63;
            atomicMax((int*)(out + (bb * T_ + t) * O_ + o), sRed[i]);
        }
        __syncthreads();                 // sRed reads done before next tile overwrites X
    }
}

// ---------------- launch ----------------
extern "C" void kernel_launch(void* const* d_in, const int* in_sizes, int n_in,
                              void* d_out, int out_size) {
    const float* P  = (const float*)d_in[0];
    const float* W1 = (const float*)d_in[1];
    const float* b1 = (const float*)d_in[2];
    const float* W2 = (const float*)d_in[3];
    const float* b2 = (const float*)d_in[4];
    const float* W3 = (const float*)d_in[5];
    const float* b3 = (const float*)d_in[6];
    float* out = (float*)d_out;

    cudaFuncSetAttribute(mlp_main_kernel, cudaFuncAttributeMaxDynamicSharedMemorySize, SMEM_TOTAL);
    cudaFuncSetAttribute(compute_pw_mma, cudaFuncAttributeMaxDynamicSharedMemorySize, PWK_SMEM);

    prep_weights<<<(9 * 144 * NSTRIDE + 255) / 256, 256>>>(W1, W2, W3);
    build_map<<<1, 128>>>();
    compute_pre_kernel<<<(T_ * BB_ * D_) / 256, 256>>>(P, out);
    compute_pw_mma<<<T_ / 4, 256, PWK_SMEM>>>(P, b1);
    mlp_main_kernel<<<148, 512, SMEM_TOTAL>>>(P, b2, b3, out);
}

// round 14
// speedup vs baseline: 1.1261x; 1.1261x over previous
#include <cuda_runtime.h>
#include <cuda_fp16.h>
#include <math.h>
#include <stdint.h>

#define BB_ 32
#define T_ 128
#define D_ 128
#define H_ 132
#define O_ 64

#define NSTRIDE 24                    // fp16 per n-row (48B): [16 k-vals][8B pad] -> ldmatrix conflict-free
#define WCH_AB (144 * 48)             // 6912 B per k-step chunk (N=144)
#define WCH_C  (64 * 48)              // 3072 B per k-step chunk (N=64)
#define WBYTES_A (8 * WCH_AB)         // 55296
#define WBYTES_B (9 * WCH_AB)         // 62208
#define WBYTES_C (9 * WCH_C)          // 27648

// ---------------- main-kernel SMEM layout ----------------
#define OFF_X   0                     // 9 ksteps x 128 rows x 32B = 36864
#define OFF_W   36864                 // whole-stage weights, max 62208 -> 99072
#define OFF_B2  99072                 // 144 floats -> 99648
#define OFF_B3  99648                 // 64 floats  -> 99904
#define OFF_RED OFF_X                 // sRed (8192B) ALIASES X tile; used only after stage C
#define SMEM_TOTAL 99904              // x2 blocks = 199808 < 228KB/SM

// ---------------- PW-kernel SMEM layout ----------------
#define PWK_W   36864                 // W (55296) -> 92160
#define PWK_XL  92160                 // Xl (32768) -> 124928
#define PWK_B1  124928                // 144 floats -> 125504
#define PWK_SMEM 125504

#define NBLK 2112                     // sum_t ceil((128-t)/4)

// ---------------- device scratch ----------------
__device__ float g_B4[4 * 32 * BB_ * D_];      // [p][j][bb][d]: max P over s in [4j+p, 4j+4+p)
__device__ float g_pre4[T_ * 32 * BB_ * D_];   // [t][ci][bb][d]: max over [t, t+4(ci+1))
__device__ float g_PW[T_ * BB_ * 144];         // [s][bb][n]: P(s,bb)·W1[128:256] + b1
__device__ __half g_W1h[8 * 144 * NSTRIDE];    // [kstep][n][24], W1 rows 0..127 (M part), fp16
__device__ __half g_W1pw[8 * 144 * NSTRIDE];   // [kstep][n][24], W1 rows 128..255 (P part), fp16
__device__ __half g_W2h[9 * 144 * NSTRIDE];
__device__ __half g_W3h[9 * 64 * NSTRIDE];
__device__ int g_map[NBLK];                    // packed (t<<8)|c

// ---------------- asm helpers ----------------
__device__ __forceinline__ void mma_f16(float d[4], const uint32_t a[4], const uint32_t b[2]) {
    asm volatile("mma.sync.aligned.m16n8k16.row.col.f32.f16.f16.f32 "
                 "{%0,%1,%2,%3}, {%4,%5,%6,%7}, {%8,%9}, {%0,%1,%2,%3};"
                 : "+f"(d[0]), "+f"(d[1]), "+f"(d[2]), "+f"(d[3])
                 : "r"(a[0]), "r"(a[1]), "r"(a[2]), "r"(a[3]), "r"(b[0]), "r"(b[1]));
}
__device__ __forceinline__ uint32_t smem_u32(const void* p) {
    uint32_t a;
    asm("{ .reg .u64 t; cvta.to.shared.u64 t, %1; cvt.u32.u64 %0, t; }" : "=r"(a) : "l"(p));
    return a;
}
#define CP16(dst, src) asm volatile("cp.async.ca.shared.global [%0], [%1], 16;" :: "r"(dst), "l"(src) : "memory")
#define CP_COMMIT()    asm volatile("cp.async.commit_group;" ::: "memory")
#define CP_WAIT0()     asm volatile("cp.async.wait_group 0;" ::: "memory")
#define LDSM4(r, a) asm volatile("ldmatrix.sync.aligned.m8n8.x4.shared.b16 {%0,%1,%2,%3}, [%4];" \
    : "=r"((r)[0]), "=r"((r)[1]), "=r"((r)[2]), "=r"((r)[3]) : "r"(a))
#define LDSM2(r, a) asm volatile("ldmatrix.sync.aligned.m8n8.x2.shared.b16 {%0,%1}, [%2];" \
    : "=r"((r)[0]), "=r"((r)[1]) : "r"(a))

// X element address with 16B-half swizzle (ldmatrix conflict-free); 128 rows/kstep
__device__ __forceinline__ int x_off(int ks, int row, int kk) {
    int phys = (kk >> 3) ^ ((row >> 2) & 1);
    return ks * 4096 + row * 32 + phys * 16 + (kk & 7) * 2;
}

// ---------------- prep: fp16 weights (N padded to 144, 48B n-stride) + tile map ----------------
__global__ void prep_weights(const float* __restrict__ W1, const float* __restrict__ W2,
                             const float* __restrict__ W3) {
    int i = blockIdx.x * blockDim.x + threadIdx.x;
    if (blockIdx.x == 0 && threadIdx.x < 128) {
        int t = threadIdx.x;
        int start = 0;
        for (int u = 0; u < t; ++u) start += (131 - u) >> 2;
        int nch = (131 - t) >> 2;
        for (int c2 = 0; c2 < nch; ++c2) g_map[start + c2] = (t << 8) | c2;
    }
    if (i < 8 * 144 * NSTRIDE) {
        int ks = i / (144 * NSTRIDE), r = i % (144 * NSTRIDE);
        int n = r / NSTRIDE, kk = r % NSTRIDE;
        __half o = __float2half(0.f), o2 = o;
        if (kk < 16 && n < H_) {
            o  = __float2half(W1[(ks * 16 + kk) * H_ + n]);
            o2 = __float2half(W1[(128 + ks * 16 + kk) * H_ + n]);
        }
        g_W1h[i] = o;
        g_W1pw[i] = o2;
    }
    if (i < 9 * 144 * NSTRIDE) {
        int ks = i / (144 * NSTRIDE), r = i % (144 * NSTRIDE);
        int n = r / NSTRIDE, kk = r % NSTRIDE;
        int k = ks * 16 + kk;
        __half o = __float2half(0.f);
        if (kk < 16 && n < H_ && k < H_) o = __float2half(W2[k * H_ + n]);
        g_W2h[i] = o;
    }
    if (i < 9 * 64 * NSTRIDE) {
        int ks = i / (64 * NSTRIDE), r = i % (64 * NSTRIDE);
        int n = r / NSTRIDE, kk = r % NSTRIDE;
        int k = ks * 16 + kk;
        __half o = __float2half(0.f);
        if (kk < 16 && k < H_) o = __float2half(W3[k * O_ + n]);
        g_W3h[i] = o;
    }
}

// ---------------- pre level 1: phase-blocked 4-maxes (+ out init folded in) ----------------
__global__ void pre_block(const float* __restrict__ P, float* __restrict__ out) {
    int idx = blockIdx.x * blockDim.x + threadIdx.x;   // 4*32*4096 = 524288
    if (idx < BB_ * T_ * O_) out[idx] = 0.f;
    int p = idx >> 17, j = (idx >> 12) & 31, bb = (idx >> 7) & 31, d = idx & 127;
    int s0 = 4 * j + p;
    float m = -3.4e38f;
    #pragma unroll
    for (int i = 0; i < 4; ++i) {
        int s = s0 + i;
        if (s < T_) m = fmaxf(m, P[(bb * T_ + s) * D_ + d]);
    }
    g_B4[idx] = m;
}

// ---------------- pre level 2: scan phase blocks into g_pre4 ----------------
__global__ void pre_combine() {
    int idx = blockIdx.x * blockDim.x + threadIdx.x;   // T_*BB_*D_ = 524288
    int t = idx >> 12, bb = (idx >> 7) & 31, d = idx & 127;
    int p = t & 3, j0 = t >> 2;
    float run = -3.4e38f;
    int nci = 32 - j0;
    float* dst = g_pre4 + ((t * 32) * BB_ + bb) * D_ + d;
    const float* src = g_B4 + ((p * 32 + j0) * BB_ + bb) * D_ + d;
    for (int ci = 0; ci < nci; ++ci) {
        run = fmaxf(run, src[ci * (BB_ * D_)]);
        dst[ci * (BB_ * D_)] = run;
    }
}

// ---------------- barrier-free GEMM stage (MT m-tiles per warp) ----------------
template <int K16, int NT, int MT, int CHUNK, int XSTR>
__device__ __forceinline__ void gemm_stage(uint32_t wbase, float (*acc)[4],
                                           const uint32_t* aH, const uint32_t* bOff) {
    #pragma unroll
    for (int k = 0; k < K16; ++k) {
        uint32_t wb = wbase + k * CHUNK;
        uint32_t ah[MT][4];
        #pragma unroll
        for (int m = 0; m < MT; ++m) LDSM4(ah[m], aH[m] + k * XSTR);
        uint32_t b[2 * NT];
        if (NT == 9) {
            LDSM4(b, wb + bOff[0]); LDSM4(b + 4, wb + bOff[1]);
            LDSM4(b + 8, wb + bOff[2]); LDSM4(b + 12, wb + bOff[3]);
            LDSM2(b + 16, wb + bOff[4]);
        } else {
            LDSM4(b, wb + bOff[0]); LDSM4(b + 4, wb + bOff[1]);
        }
        #pragma unroll
        for (int j = 0; j < NT; ++j)
            #pragma unroll
            for (int m = 0; m < MT; ++m) mma_f16(acc[m * NT + j], ah[m], b + 2 * j);
    }
}

// ---------------- bulk weight loader ----------------
__device__ __forceinline__ void load_weights(uint32_t dst, const char* Wg, int bytes, int tid) {
    for (int off = tid * 16; off < bytes; off += 4096)
        CP16(dst + off, Wg + off);
    CP_COMMIT();
}

// ---------------- PW via tensor cores: g_PW[s][bb][n] = P·W1[128:256] + b1 ----------------
// grid (32, 2): 4 s-values x 32 bb rows, N-half per blockIdx.y. 2-pass Xh+Xl fp16 split.
__global__ void __launch_bounds__(256, 1)
compute_pw_mma(const float* __restrict__ P, const float* __restrict__ b1) {
    const int s4 = blockIdx.x;
    const int nqh = blockIdx.y;
    extern __shared__ char smem[];
    uint32_t su = smem_u32(smem);
    const int tid = threadIdx.x;
    float* sB1 = (float*)(smem + PWK_B1);

    load_weights(su + PWK_W, (const char*)g_W1pw, WBYTES_A, tid);
    for (int i = tid; i < 144; i += 256) sB1[i] = (i < H_) ? b1[i] : 0.f;

    // X build: hi/lo fp16 of P, vectorized
    {
        int p = tid & 63, g = tid >> 6;
        int d0 = 2 * p, ks = d0 >> 4, kk = d0 & 15;
        char* xh = smem;
        char* xl = smem + PWK_XL;
        for (int b8 = 0; b8 < 8; ++b8) {
            int bb = g * 8 + b8;
            #pragma unroll
            for (int sl = 0; sl < 4; ++sl) {
                int s = s4 * 4 + sl;
                float2 pv = *(const float2*)&P[(bb * T_ + s) * D_ + d0];
                int row = sl * 32 + bb;
                int ph = (kk >> 3) ^ ((row >> 2) & 1);
                int off = ks * 4096 + row * 32 + ph * 16 + (kk & 7) * 2;
                __half2 h, l;
                h.x = __float2half(pv.x); h.y = __float2half(pv.y);
                l.x = __float2half(pv.x - __half2float(h.x));
                l.y = __float2half(pv.y - __half2float(h.y));
                *(__half2*)(xh + off) = h;
                *(__half2*)(xl + off) = l;
            }
        }
    }
    CP_WAIT0();
    __syncthreads();

    const int wid = tid >> 5, lane = tid & 31;
    const int m0 = wid * 16;                 // 8 m-quads, 1 m-tile each
    const int grp = lane >> 2, c0 = 2 * (lane & 3);

    uint32_t aH0, aL0, bAB[5];
    {
        int l15 = lane & 15, chnk = lane >> 4;
        int row = m0 + l15;
        int phys = chnk ^ ((row >> 2) & 1);
        aH0 = su + row * 32 + phys * 16;
        aL0 = aH0 + PWK_XL;
        int l7 = lane & 7, kh = (lane >> 3) & 1, pr = (lane >> 4) & 1;
        #pragma unroll
        for (int i = 0; i < 4; ++i)
            bAB[i] = (uint32_t)((nqh * 72 + 16 * i + pr * 8 + l7) * 48 + kh * 16);
        bAB[4] = (uint32_t)((nqh * 72 + 64 + l7) * 48 + kh * 16);
    }

    float acc[9][4];
    #pragma unroll
    for (int i = 0; i < 9; ++i) { acc[i][0] = acc[i][1] = acc[i][2] = acc[i][3] = 0.f; }
    gemm_stage<8, 9, 1, WCH_AB, 4096>(su + PWK_W, acc, &aH0, bAB);   // hi pass
    gemm_stage<8, 9, 1, WCH_AB, 4096>(su + PWK_W, acc, &aL0, bAB);   // lo pass

    #pragma unroll
    for (int rp = 0; rp < 2; ++rp) {
        int row = m0 + grp + rp * 8;
        int sl = row >> 5, bb = row & 31;
        int s = s4 * 4 + sl;
        #pragma unroll
        for (int j = 0; j < 9; ++j) {
            int n0 = nqh * 72 + j * 8 + c0;
            float2 v;
            v.x = acc[j][rp * 2 + 0] + sB1[n0];
            v.y = acc[j][rp * 2 + 1] + sB1[n0 + 1];
            *(float2*)&g_PW[(s * BB_ + bb) * 144 + n0] = v;
        }
    }
}

// ---------------- relu epilogue: write fp16 X tile for next stage ----------------
__device__ __forceinline__ void epi_relu(char* smem, float (*acc)[4], const float* bias,
                                         int m0, int nbase, int lane) {
    char* xh = smem + OFF_X;
    const int grp = lane >> 2;
    const int c0 = 2 * (lane & 3);
    #pragma unroll
    for (int mt = 0; mt < 2; ++mt)
    #pragma unroll
    for (int j = 0; j < 9; ++j) {
        int n0 = nbase + j * 8 + c0;
        float bv0 = bias ? bias[n0] : 0.f;
        float bv1 = bias ? bias[n0 + 1] : 0.f;
        int ks = n0 >> 4, kk = n0 & 15;
        #pragma unroll
        for (int rp = 0; rp < 2; ++rp) {
            int row = m0 + mt * 64 + grp + rp * 8;
            float v0 = fmaxf(acc[mt * 9 + j][rp * 2 + 0] + bv0, 0.f);
            float v1 = fmaxf(acc[mt * 9 + j][rp * 2 + 1] + bv1, 0.f);
            __half2 hp; hp.x = __float2half(v0); hp.y = __float2half(v1);
            *(__half2*)(xh + x_off(ks, row, kk)) = hp;
        }
    }
}

// ---------------- main (R12 structure: 2112 blocks, whole-stage resident W) ----------------
__global__ void __launch_bounds__(256, 2)
mlp_main_kernel(const float* __restrict__ P,
                const float* __restrict__ b2, const float* __restrict__ b3,
                float* __restrict__ out) {
    const int mc = g_map[blockIdx.x];
    const int t = mc >> 8;
    const int c = mc & 255;
    const int s0 = t + 4 * c;

    extern __shared__ char smem[];
    uint32_t su = smem_u32(smem);
    const int tid = threadIdx.x;
    float* sB2 = (float*)(smem + OFF_B2);
    float* sB3 = (float*)(smem + OFF_B3);
    int* sRed = (int*)(smem + OFF_RED);    // ALIASES X tile; valid only after stage C

    load_weights(su + OFF_W, (const char*)g_W1h, WBYTES_A, tid);

    for (int i = tid; i < 144; i += 256) sB2[i] = (i < H_) ? b2[i] : 0.f;
    if (tid < 64) sB3[tid] = b3[tid];

    // feature build (vectorized): rows r = sl*32+bb; K cols [0,128) = running max, fp16
    {
        int p = tid & 63, g = tid >> 6;
        int d0 = 2 * p, ks = d0 >> 4, kk = d0 & 15;
        char* xh = smem + OFF_X;
        for (int b8 = 0; b8 < 8; ++b8) {
            int bb = g * 8 + b8;
            float2 run2;
            if (c > 0) run2 = *(const float2*)&g_pre4[((t * 32 + (c - 1)) * BB_ + bb) * D_ + d0];
            else { run2.x = -3.4e38f; run2.y = -3.4e38f; }
            #pragma unroll
            for (int sl = 0; sl < 4; ++sl) {
                int s = s0 + sl;
                if (s < T_) {
                    float2 pv = *(const float2*)&P[(bb * T_ + s) * D_ + d0];
                    run2.x = fmaxf(run2.x, pv.x);
                    run2.y = fmaxf(run2.y, pv.y);
                }
                int row = sl * 32 + bb;
                int ph = (kk >> 3) ^ ((row >> 2) & 1);
                int off = ks * 4096 + row * 32 + ph * 16 + (kk & 7) * 2;
                __half2 hp; hp.x = __float2half(run2.x); hp.y = __float2half(run2.y);
                *(__half2*)(xh + off) = hp;
            }
        }
    }
    CP_WAIT0();
    __syncthreads();

    const int wid = tid >> 5, lane = tid & 31;
    const int mq = wid >> 1, nq = wid & 1;      // 4 m-quads x 2 n-halves; m-tiles at m0, m0+64
    const int m0 = mq * 16;
    const int grp = lane >> 2, c0 = 2 * (lane & 3);

    uint32_t aH[2], bAB[5], bC[2];
    {
        int l15 = lane & 15, chnk = lane >> 4;
        #pragma unroll
        for (int mt = 0; mt < 2; ++mt) {
            int row = m0 + mt * 64 + l15;
            int phys = chnk ^ ((row >> 2) & 1);
            aH[mt] = su + OFF_X + row * 32 + phys * 16;
        }
        int l7 = lane & 7, kh = (lane >> 3) & 1, pr = (lane >> 4) & 1;
        #pragma unroll
        for (int i = 0; i < 4; ++i)
            bAB[i] = (uint32_t)((nq * 72 + 16 * i + pr * 8 + l7) * 48 + kh * 16);
        bAB[4] = (uint32_t)((nq * 72 + 64 + l7) * 48 + kh * 16);
        #pragma unroll
        for (int i = 0; i < 2; ++i)
            bC[i] = (uint32_t)((nq * 32 + 16 * i + pr * 8 + l7) * 48 + kh * 16);
    }

    float acc[18][4];

    // Stage A: acc preloaded from PW (P-part + b1), K=128 M-part only
    #pragma unroll
    for (int mt = 0; mt < 2; ++mt) {
        int r_lo = m0 + mt * 64 + grp, r_hi = r_lo + 8;
        int s_lo = min(s0 + (r_lo >> 5), T_ - 1), s_hi = min(s0 + (r_hi >> 5), T_ - 1);
        const float* pwlo = g_PW + (s_lo * BB_ + (r_lo & 31)) * 144;
        const float* pwhi = g_PW + (s_hi * BB_ + (r_hi & 31)) * 144;
        #pragma unroll
        for (int j = 0; j < 9; ++j) {
            int n0 = nq * 72 + j * 8 + c0;
            float2 vlo = *(const float2*)(pwlo + n0);
            float2 vhi = *(const float2*)(pwhi + n0);
            acc[mt * 9 + j][0] = vlo.x; acc[mt * 9 + j][1] = vlo.y;
            acc[mt * 9 + j][2] = vhi.x; acc[mt * 9 + j][3] = vhi.y;
        }
    }
    gemm_stage<8, 9, 2, WCH_AB, 4096>(su + OFF_W, acc, aH, bAB);
    __syncthreads();
    load_weights(su + OFF_W, (const char*)g_W2h, WBYTES_B, tid);   // hide behind epi A
    epi_relu(smem, acc, (const float*)0, m0, nq * 72, lane);
    CP_WAIT0();
    __syncthreads();

    // Stage B: K=144 (9 ksteps), N=144
    #pragma unroll
    for (int i = 0; i < 18; ++i) { acc[i][0] = acc[i][1] = acc[i][2] = acc[i][3] = 0.f; }
    gemm_stage<9, 9, 2, WCH_AB, 4096>(su + OFF_W, acc, aH, bAB);
    __syncthreads();
    load_weights(su + OFF_W, (const char*)g_W3h, WBYTES_C, tid);   // hide behind epi B
    epi_relu(smem, acc, sB2, m0, nq * 72, lane);
    CP_WAIT0();
    __syncthreads();

    // Stage C: K=144 (9 ksteps), N=64
    #pragma unroll
    for (int i = 0; i < 8; ++i) { acc[i][0] = acc[i][1] = acc[i][2] = acc[i][3] = 0.f; }
    gemm_stage<9, 4, 2, WCH_C, 4096>(su + OFF_W, acc, aH, bC);

    // X tile is dead now; init the aliased reduction buffer, then reduce
    __syncthreads();
    for (int i = tid; i < BB_ * O_; i += 256) sRed[i] = 0;
    __syncthreads();

    // final epilogue: sigmoid + max reduce
    {
        #pragma unroll
        for (int mt = 0; mt < 2; ++mt)
        #pragma unroll
        for (int rp = 0; rp < 2; ++rp) {
            int row = m0 + mt * 64 + grp + rp * 8;
            int sl = row >> 5, bb = row & 31;
            if (s0 + sl < T_) {
                #pragma unroll
                for (int j = 0; j < 4; ++j) {
                    int n0 = nq * 32 + j * 8 + c0;
                    float y0 = 1.f / (1.f + __expf(-5.f * (acc[mt * 4 + j][rp * 2 + 0] + sB3[n0])));
                    float y1 = 1.f / (1.f + __expf(-5.f * (acc[mt * 4 + j][rp * 2 + 1] + sB3[n0 + 1])));
                    atomicMax(&sRed[bb * O_ + n0], __float_as_int(y0));
                    atomicMax(&sRed[bb * O_ + n0 + 1], __float_as_int(y1));
                }
            }
        }
    }
    __syncthreads();
    for (int i = tid; i < BB_ * O_; i += 256) {
        int bb = i >> 6, o = i & 63;
        atomicMax((int*)(out + (bb * T_ + t) * O_ + o), sRed[i]);
    }
}

// ---------------- launch ----------------
extern "C" void kernel_launch(void* const* d_in, const int* in_sizes, int n_in,
                              void* d_out, int out_size) {
    const float* P  = (const float*)d_in[0];
    const float* W1 = (const float*)d_in[1];
    const float* b1 = (const float*)d_in[2];
    const float* W2 = (const float*)d_in[3];
    const float* b2 = (const float*)d_in[4];
    const float* W3 = (const float*)d_in[5];
    const float* b3 = (const float*)d_in[6];
    float* out = (float*)d_out;

    cudaFuncSetAttribute(mlp_main_kernel, cudaFuncAttributeMaxDynamicSharedMemorySize, SMEM_TOTAL);
    cudaFuncSetAttribute(compute_pw_mma, cudaFuncAttributeMaxDynamicSharedMemorySize, PWK_SMEM);

    prep_weights<<<(9 * 144 * NSTRIDE + 255) / 256, 256>>>(W1, W2, W3);
    pre_block<<<(4 * 32 * BB_ * D_) / 256, 256>>>(P, out);
    pre_combine<<<(T_ * BB_ * D_) / 256, 256>>>();
    compute_pw_mma<<<dim3(32, 2), 256, PWK_SMEM>>>(P, b1);
    mlp_main_kernel<<<NBLK, 256, SMEM_TOTAL>>>(P, b2, b3, out);
}